// round 1
// baseline (speedup 1.0000x reference)
#include <cuda_runtime.h>

#define cN0 200000
#define cN1 50000
#define cN2 10000
#define cL  10
#define cE0 800000
#define cE1 160000
#define cIN 128
#define cU  32
#define cLP 128

// ---------------- scratch (device globals; no runtime allocation) ----------------
__device__ float g_h0[(size_t)cN0 * 160];      // layer-0 node features [e_relu(128) | unsup(32)]
__device__ float g_h1feat[(size_t)cN1 * 256];  // relu(conv0 out_feat)
__device__ float g_un0[(size_t)cN1 * 32];      // conv0 aggregated unsup (layer-1 un)
__device__ float g_h2[(size_t)cN2 * 256];      // conv1 out_feat (no relu)
__device__ float g_X0[(size_t)cN1 * 256];      // [agg_feat(128) | tgt_feat(128)]
__device__ float g_X1[(size_t)cN2 * 512];      // [agg_feat(256) | tgt_feat(256)]
__device__ float g_A[cE0];                     // edge attention (reused for conv1)
__device__ int   g_eidx[cE0];
__device__ int   g_rowptr[cN1 + 1];
__device__ int   g_deg[cN1];
__device__ int   g_cursor[cN1];
__device__ float g_W0[256 * 256];              // vstack(ll_w0.T, lr_w0.T)
__device__ float g_W1[512 * 256];              // vstack(ll_w1.T, lr_w1.T)

// ---------------- embedding bag + LN + relu + concat unsup ----------------
__global__ void k_embed(const int* __restrict__ x, const float* __restrict__ xu,
                        const float* __restrict__ tab, const float* __restrict__ g,
                        const float* __restrict__ b) {
  int n = blockIdx.x;
  int t = threadIdx.x;  // 128 threads
  __shared__ int sidx[cL];
  __shared__ float ss[4], qq[4];
  if (t < cL) sidx[t] = x[n * cL + t];
  __syncthreads();
  float v = 0.f;
#pragma unroll
  for (int l = 0; l < cL; l++) {
    int id = sidx[l];
    if (id != 0) v += tab[(size_t)id * cIN + t];  // row 0 masked to zero
  }
  float s = v, q = v * v;
#pragma unroll
  for (int o = 16; o; o >>= 1) {
    s += __shfl_xor_sync(0xffffffffu, s, o);
    q += __shfl_xor_sync(0xffffffffu, q, o);
  }
  if ((t & 31) == 0) { ss[t >> 5] = s; qq[t >> 5] = q; }
  __syncthreads();
  float S = ss[0] + ss[1] + ss[2] + ss[3];
  float Q = qq[0] + qq[1] + qq[2] + qq[3];
  float m = S * (1.f / cIN);
  float rs = rsqrtf(Q * (1.f / cIN) - m * m + 1e-5f);
  float ov = (v - m) * rs * g[t] + b[t];
  float* row = g_h0 + (size_t)n * 160;
  row[t] = fmaxf(ov, 0.f);
  if (t < cU) row[cIN + t] = xu[(size_t)n * cU + t];
}

// ---------------- CSR build ----------------
__global__ void k_zero_deg(int n) {
  int i = blockIdx.x * blockDim.x + threadIdx.x;
  if (i < n) g_deg[i] = 0;
}
__global__ void k_hist(const int* __restrict__ dst, int E) {
  int i = blockIdx.x * blockDim.x + threadIdx.x;
  if (i < E) atomicAdd(&g_deg[dst[i]], 1);
}
__global__ void k_scan(int n, int E) {  // single block, 1024 threads
  __shared__ int sh[1024];
  int t = threadIdx.x;
  int chunk = (n + 1023) / 1024;
  int beg = t * chunk;
  int end = beg + chunk; if (end > n) end = n; if (beg > n) beg = n;
  int local = 0;
  for (int i = beg; i < end; i++) local += g_deg[i];
  sh[t] = local;
  __syncthreads();
  for (int off = 1; off < 1024; off <<= 1) {
    int v = (t >= off) ? sh[t - off] : 0;
    __syncthreads();
    sh[t] += v;
    __syncthreads();
  }
  int offset = (t == 0) ? 0 : sh[t - 1];
  for (int i = beg; i < end; i++) {
    g_rowptr[i] = offset;
    g_cursor[i] = offset;
    offset += g_deg[i];
  }
  if (t == 0) g_rowptr[n] = E;
}
__global__ void k_scatter(const int* __restrict__ dst, int E) {
  int i = blockIdx.x * blockDim.x + threadIdx.x;
  if (i < E) {
    int pos = atomicAdd(&g_cursor[dst[i]], 1);
    g_eidx[pos] = i;
  }
}

// ---------------- per-edge LP attention MLP (4 edges per warp) ----------------
// smem layout (floats): w1T[96*128] | b1[128] | g[128] | bn[128] | w2[128] | hc[8*384]
__global__ void k_edge_lp(const int* __restrict__ src, const int* __restrict__ dst, int E,
                          const float* __restrict__ usrc, int sstr, int soff,
                          const float* __restrict__ utgt, int tstr, int toff,
                          const float* __restrict__ w1, const float* __restrict__ b1,
                          const float* __restrict__ lg, const float* __restrict__ lbn,
                          const float* __restrict__ w2, const float* __restrict__ b2p) {
  extern __shared__ float sm[];
  float* w1T = sm;                 // [96][128]  w1T[c*128+o] = w1[o*96+c]
  float* b1s = sm + 96 * 128;
  float* gs  = b1s + 128;
  float* bns = gs + 128;
  float* w2s = bns + 128;
  float* hc  = w2s + 128;          // [warps][96][4]

  for (int i = threadIdx.x; i < 96 * 128; i += blockDim.x) {
    int c = i >> 7, o = i & 127;
    w1T[i] = w1[o * 96 + c];
  }
  for (int i = threadIdx.x; i < 128; i += blockDim.x) {
    b1s[i] = b1[i]; gs[i] = lg[i]; bns[i] = lbn[i]; w2s[i] = w2[i];
  }
  __syncthreads();

  int lane = threadIdx.x & 31;
  int w = threadIdx.x >> 5;
  float* myh = hc + w * 384;
  float b2v = b2p[0];
  float4 bv  = ((const float4*)b1s)[lane];
  float4 gv  = ((const float4*)gs)[lane];
  float4 bnv = ((const float4*)bns)[lane];
  float4 w2v = ((const float4*)w2s)[lane];
  int warps_tot = gridDim.x * (blockDim.x >> 5);

  for (long base = ((long)blockIdx.x * (blockDim.x >> 5) + w) * 4; base < E;
       base += (long)warps_tot * 4) {
#pragma unroll
    for (int t = 0; t < 4; t++) {
      long ee = base + t;
      int e = (ee < E) ? (int)ee : (E - 1);
      int sn = src[e], dn = dst[e];
      float uj = usrc[(size_t)sn * sstr + soff + lane];
      float ui = utgt[(size_t)dn * tstr + toff + lane];
      myh[(lane << 2) + t] = fabsf(ui - uj);
      myh[((32 + lane) << 2) + t] = ui + uj;
      myh[((64 + lane) << 2) + t] = ui * uj;
    }
    __syncwarp();
    float acc[4][4];
#pragma unroll
    for (int t = 0; t < 4; t++) { acc[t][0] = bv.x; acc[t][1] = bv.y; acc[t][2] = bv.z; acc[t][3] = bv.w; }
#pragma unroll 8
    for (int c = 0; c < 96; c++) {
      float4 wv = *(const float4*)(w1T + (c << 7) + (lane << 2));
      float4 hv = *(const float4*)(myh + (c << 2));
      acc[0][0] = fmaf(wv.x, hv.x, acc[0][0]); acc[0][1] = fmaf(wv.y, hv.x, acc[0][1]);
      acc[0][2] = fmaf(wv.z, hv.x, acc[0][2]); acc[0][3] = fmaf(wv.w, hv.x, acc[0][3]);
      acc[1][0] = fmaf(wv.x, hv.y, acc[1][0]); acc[1][1] = fmaf(wv.y, hv.y, acc[1][1]);
      acc[1][2] = fmaf(wv.z, hv.y, acc[1][2]); acc[1][3] = fmaf(wv.w, hv.y, acc[1][3]);
      acc[2][0] = fmaf(wv.x, hv.z, acc[2][0]); acc[2][1] = fmaf(wv.y, hv.z, acc[2][1]);
      acc[2][2] = fmaf(wv.z, hv.z, acc[2][2]); acc[2][3] = fmaf(wv.w, hv.z, acc[2][3]);
      acc[3][0] = fmaf(wv.x, hv.w, acc[3][0]); acc[3][1] = fmaf(wv.y, hv.w, acc[3][1]);
      acc[3][2] = fmaf(wv.z, hv.w, acc[3][2]); acc[3][3] = fmaf(wv.w, hv.w, acc[3][3]);
    }
#pragma unroll
    for (int t = 0; t < 4; t++) {
      float S = acc[t][0] + acc[t][1] + acc[t][2] + acc[t][3];
      float Q = acc[t][0] * acc[t][0] + acc[t][1] * acc[t][1] +
                acc[t][2] * acc[t][2] + acc[t][3] * acc[t][3];
#pragma unroll
      for (int o = 16; o; o >>= 1) {
        S += __shfl_xor_sync(0xffffffffu, S, o);
        Q += __shfl_xor_sync(0xffffffffu, Q, o);
      }
      float m = S * (1.f / 128.f);
      float rs = rsqrtf(Q * (1.f / 128.f) - m * m + 1e-5f);
      float p = fmaxf((acc[t][0] - m) * rs * gv.x + bnv.x, 0.f) * w2v.x +
                fmaxf((acc[t][1] - m) * rs * gv.y + bnv.y, 0.f) * w2v.y +
                fmaxf((acc[t][2] - m) * rs * gv.z + bnv.z, 0.f) * w2v.z +
                fmaxf((acc[t][3] - m) * rs * gv.w + bnv.w, 0.f) * w2v.w;
#pragma unroll
      for (int o = 16; o; o >>= 1) p += __shfl_xor_sync(0xffffffffu, p, o);
      if (lane == 0 && base + t < E) g_A[base + t] = 1.f / (1.f + expf(-(p + b2v)));
    }
    __syncwarp();
  }
}

// ---------------- gather-side aggregation (1 warp per dst, no atomics) ----------------
__global__ void k_agg0(const int* __restrict__ src) {
  int gw = (blockIdx.x * blockDim.x + threadIdx.x) >> 5;
  int lane = threadIdx.x & 31;
  if (gw >= cN1) return;
  int beg = g_rowptr[gw], end = g_rowptr[gw + 1];
  float asum = 0.f;
  for (int i = beg + lane; i < end; i += 32) asum += g_A[g_eidx[i]];
#pragma unroll
  for (int o = 16; o; o >>= 1) asum += __shfl_xor_sync(0xffffffffu, asum, o);
  float inv = (end > beg) ? 1.f / asum : 0.f;
  float a0 = 0.f, a1 = 0.f, a2 = 0.f, a3 = 0.f, au = 0.f;
  for (int i = beg; i < end; i++) {
    int e = g_eidx[i];
    const float* row = g_h0 + (size_t)src[e] * 160;
    float a = g_A[e] * inv;
    a0 = fmaf(a, row[lane], a0);
    a1 = fmaf(a, row[32 + lane], a1);
    a2 = fmaf(a, row[64 + lane], a2);
    a3 = fmaf(a, row[96 + lane], a3);
    au += row[128 + lane];
  }
  float* X = g_X0 + (size_t)gw * 256;
  X[lane] = a0; X[32 + lane] = a1; X[64 + lane] = a2; X[96 + lane] = a3;
  const float* ht = g_h0 + (size_t)gw * 160;
  X[128 + lane] = ht[lane];
  X[160 + lane] = ht[32 + lane];
  X[192 + lane] = ht[64 + lane];
  X[224 + lane] = ht[96 + lane];
  g_un0[(size_t)gw * 32 + lane] = au;
}

__global__ void k_agg1(const int* __restrict__ src) {
  int gw = (blockIdx.x * blockDim.x + threadIdx.x) >> 5;
  int lane = threadIdx.x & 31;
  if (gw >= cN2) return;
  int beg = g_rowptr[gw], end = g_rowptr[gw + 1];
  float asum = 0.f;
  for (int i = beg + lane; i < end; i += 32) asum += g_A[g_eidx[i]];
#pragma unroll
  for (int o = 16; o; o >>= 1) asum += __shfl_xor_sync(0xffffffffu, asum, o);
  float inv = (end > beg) ? 1.f / asum : 0.f;
  float acc[8] = {0.f, 0.f, 0.f, 0.f, 0.f, 0.f, 0.f, 0.f};
  for (int i = beg; i < end; i++) {
    int e = g_eidx[i];
    const float* row = g_h1feat + (size_t)src[e] * 256;
    float a = g_A[e] * inv;
#pragma unroll
    for (int k = 0; k < 8; k++) acc[k] = fmaf(a, row[(k << 5) + lane], acc[k]);
  }
  float* X = g_X1 + (size_t)gw * 512;
  const float* ht = g_h1feat + (size_t)gw * 256;
#pragma unroll
  for (int k = 0; k < 8; k++) {
    X[(k << 5) + lane] = acc[k];
    X[256 + (k << 5) + lane] = ht[(k << 5) + lane];
  }
}

// ---------------- weight concat: W[k][n] = k<K2 ? ll[n][k] : lr[n][k-K2] ----------------
__global__ void k_prepw(const float* __restrict__ ll, const float* __restrict__ lr,
                        float* __restrict__ W, int K2, int N) {
  int i = blockIdx.x * blockDim.x + threadIdx.x;
  int total = 2 * K2 * N;
  if (i >= total) return;
  int k = i / N, n = i % N;
  W[i] = (k < K2) ? ll[n * K2 + k] : lr[n * K2 + (k - K2)];
}

// ---------------- simple tiled SGEMM: C[M,N] = X[M,K] @ W[K,N] + bias, optional relu ----------------
__global__ __launch_bounds__(256) void k_gemm(const float* __restrict__ X,
                                              const float* __restrict__ W,
                                              const float* __restrict__ bias,
                                              float* __restrict__ C,
                                              int M, int K, int N, int do_relu) {
  __shared__ float As[16][64];
  __shared__ float Bs[16][64];
  int tid = threadIdx.x;
  int tx = tid & 15, ty = tid >> 4;
  int bm = blockIdx.y << 6, bn = blockIdx.x << 6;
  float acc[4][4] = {};
  for (int k0 = 0; k0 < K; k0 += 16) {
#pragma unroll
    for (int i = tid; i < 1024; i += 256) {
      int m = i >> 4, kk = i & 15;
      As[kk][m] = (bm + m < M) ? X[(size_t)(bm + m) * K + k0 + kk] : 0.f;
    }
#pragma unroll
    for (int i = tid; i < 1024; i += 256) {
      int kk = i >> 6, n = i & 63;
      Bs[kk][n] = W[(size_t)(k0 + kk) * N + bn + n];
    }
    __syncthreads();
#pragma unroll
    for (int kk = 0; kk < 16; kk++) {
      float4 av = *(const float4*)&As[kk][ty << 2];
      float4 bvv = *(const float4*)&Bs[kk][tx << 2];
      float a[4] = {av.x, av.y, av.z, av.w};
      float bb[4] = {bvv.x, bvv.y, bvv.z, bvv.w};
#pragma unroll
      for (int i = 0; i < 4; i++)
#pragma unroll
        for (int j = 0; j < 4; j++) acc[i][j] = fmaf(a[i], bb[j], acc[i][j]);
    }
    __syncthreads();
  }
#pragma unroll
  for (int i = 0; i < 4; i++) {
    int m = bm + (ty << 2) + i;
    if (m >= M) continue;
#pragma unroll
    for (int j = 0; j < 4; j++) {
      int n = bn + (tx << 2) + j;
      float v = acc[i][j] + bias[n];
      if (do_relu) v = fmaxf(v, 0.f);
      C[(size_t)m * N + n] = v;
    }
  }
}

// ---------------- final projection ----------------
__global__ void k_final(const float* __restrict__ outw, const float* __restrict__ outb,
                        float* __restrict__ out) {
  int gw = (blockIdx.x * blockDim.x + threadIdx.x) >> 5;
  int lane = threadIdx.x & 31;
  if (gw >= cN2) return;
  const float* row = g_h2 + (size_t)gw * 256;
  float p = 0.f;
#pragma unroll
  for (int k = 0; k < 8; k++) p = fmaf(row[(k << 5) + lane], outw[(k << 5) + lane], p);
#pragma unroll
  for (int o = 16; o; o >>= 1) p += __shfl_xor_sync(0xffffffffu, p, o);
  if (lane == 0) out[gw] = p + outb[0];
}

extern "C" void kernel_launch(void* const* d_in, const int* in_sizes, int n_in,
                              void* d_out, int out_size) {
  const int*   x    = (const int*)d_in[0];
  const float* xu   = (const float*)d_in[1];
  const int*   src0 = (const int*)d_in[2];
  const int*   dst0 = (const int*)d_in[3];
  const int*   src1 = (const int*)d_in[4];
  const int*   dst1 = (const int*)d_in[5];
  const float* tab  = (const float*)d_in[6];
  const float* lng  = (const float*)d_in[7];
  const float* lnb  = (const float*)d_in[8];
  const float* lpw1 = (const float*)d_in[9];
  const float* lpb1 = (const float*)d_in[10];
  const float* lpg  = (const float*)d_in[11];
  const float* lpbn = (const float*)d_in[12];
  const float* lpw2 = (const float*)d_in[13];
  const float* lpb2 = (const float*)d_in[14];
  const float* llw0 = (const float*)d_in[15];
  const float* llb0 = (const float*)d_in[16];
  const float* lrw0 = (const float*)d_in[17];
  const float* llw1 = (const float*)d_in[18];
  const float* llb1 = (const float*)d_in[19];
  const float* lrw1 = (const float*)d_in[20];
  const float* outw = (const float*)d_in[21];
  const float* outb = (const float*)d_in[22];
  float* out = (float*)d_out;

  // symbol addresses for pointer-parameter kernels (host-side, capture-safe)
  float *p_h0, *p_un0, *p_X0, *p_X1, *p_W0, *p_W1, *p_h1, *p_h2;
  cudaGetSymbolAddress((void**)&p_h0, g_h0);
  cudaGetSymbolAddress((void**)&p_un0, g_un0);
  cudaGetSymbolAddress((void**)&p_X0, g_X0);
  cudaGetSymbolAddress((void**)&p_X1, g_X1);
  cudaGetSymbolAddress((void**)&p_W0, g_W0);
  cudaGetSymbolAddress((void**)&p_W1, g_W1);
  cudaGetSymbolAddress((void**)&p_h1, g_h1feat);
  cudaGetSymbolAddress((void**)&p_h2, g_h2);

  const int LP_SMEM = (96 * 128 + 4 * 128 + 8 * 384) * 4;  // 63488 B
  cudaFuncSetAttribute(k_edge_lp, cudaFuncAttributeMaxDynamicSharedMemorySize, LP_SMEM);

  // node features
  k_embed<<<cN0, 128>>>(x, xu, tab, lng, lnb);
  // weight concats
  k_prepw<<<(2 * 128 * 256 + 255) / 256, 256>>>(llw0, lrw0, p_W0, 128, 256);
  k_prepw<<<(2 * 256 * 256 + 255) / 256, 256>>>(llw1, lrw1, p_W1, 256, 256);

  // ---- conv layer 0 ----
  k_zero_deg<<<(cN1 + 255) / 256, 256>>>(cN1);
  k_hist<<<(cE0 + 255) / 256, 256>>>(dst0, cE0);
  k_scan<<<1, 1024>>>(cN1, cE0);
  k_scatter<<<(cE0 + 255) / 256, 256>>>(dst0, cE0);
  k_edge_lp<<<444, 256, LP_SMEM>>>(src0, dst0, cE0,
                                   p_h0, 160, 128, p_h0, 160, 128,
                                   lpw1, lpb1, lpg, lpbn, lpw2, lpb2);
  k_agg0<<<(cN1 * 32 + 255) / 256, 256>>>(src0);
  {
    dim3 grid(256 / 64, (cN1 + 63) / 64);
    k_gemm<<<grid, 256>>>(p_X0, p_W0, llb0, p_h1, cN1, 256, 256, 1);
  }

  // ---- conv layer 1 ----
  k_zero_deg<<<(cN2 + 255) / 256, 256>>>(cN2);
  k_hist<<<(cE1 + 255) / 256, 256>>>(dst1, cE1);
  k_scan<<<1, 1024>>>(cN2, cE1);
  k_scatter<<<(cE1 + 255) / 256, 256>>>(dst1, cE1);
  k_edge_lp<<<444, 256, LP_SMEM>>>(src1, dst1, cE1,
                                   p_un0, 32, 0, p_un0, 32, 0,
                                   lpw1, lpb1, lpg, lpbn, lpw2, lpb2);
  k_agg1<<<(cN2 * 32 + 255) / 256, 256>>>(src1);
  {
    dim3 grid(256 / 64, (cN2 + 63) / 64);
    k_gemm<<<grid, 256>>>(p_X1, p_W1, llb1, p_h2, cN2, 512, 256, 0);
  }

  // ---- output ----
  k_final<<<(cN2 * 32 + 255) / 256, 256>>>(outw, outb, out);
}